// round 1
// baseline (speedup 1.0000x reference)
#include <cuda_runtime.h>

// Problem constants (fixed by the reference): B=8, C=64, H=W=256.
#define Bn   8
#define Cn   64
#define Hn   256
#define Wn   256
#define HWn  (Hn * Wn)          // 65536
#define NPIX (Bn * HWn)         // 524288 = 2^19
#define CPT  8                  // channels per thread
#define NCG  (Cn / CPT)         // 8 channel groups

__global__ __launch_bounds__(256)
void warp_bilinear_kernel(const float* __restrict__ phi,
                          const float* __restrict__ x_enc,
                          const float* __restrict__ m,
                          float* __restrict__ out)
{
    const int t   = blockIdx.x * blockDim.x + threadIdx.x;
    const int pix = t & (NPIX - 1);       // low bits: pixel -> coalesced
    const int cg  = t >> 19;              // channel group 0..7
    const int b   = pix >> 16;            // pix / HW
    const int hw  = pix & (HWn - 1);
    const int h   = hw >> 8;
    const int w   = hw & (Wn - 1);

    // Per-pixel (channel-invariant) sampling setup
    const float px = phi[(b * 2 + 0) * HWn + hw];
    const float py = phi[(b * 2 + 1) * HWn + hw];
    const float mv = m[b * HWn + hw];

    // vgrid = 2*(coord+phi)/(dim-1) - 1 + 2*phi ; then unnormalize align_corners=False
    const float vx = 2.0f * ((float)w + px) / (float)(Wn - 1) - 1.0f + 2.0f * px;
    const float vy = 2.0f * ((float)h + py) / (float)(Hn - 1) - 1.0f + 2.0f * py;
    const float ix = (vx + 1.0f) * (0.5f * (float)Wn) - 0.5f;
    const float iy = (vy + 1.0f) * (0.5f * (float)Hn) - 0.5f;

    const float x0f = floorf(ix);
    const float y0f = floorf(iy);
    const int   x0  = (int)x0f;
    const int   y0  = (int)y0f;
    const int   x1  = x0 + 1;
    const int   y1  = y0 + 1;

    const float wx1 = ix - x0f;
    const float wx0 = 1.0f - wx1;
    const float wy1 = iy - y0f;
    const float wy0 = 1.0f - wy1;

    const float vx0 = (x0 >= 0 && x0 < Wn) ? 1.0f : 0.0f;
    const float vx1 = (x1 >= 0 && x1 < Wn) ? 1.0f : 0.0f;
    const float vy0 = (y0 >= 0 && y0 < Hn) ? 1.0f : 0.0f;
    const float vy1 = (y1 >= 0 && y1 < Hn) ? 1.0f : 0.0f;

    // Fold validity AND mask into the 4 corner weights (zeros padding, out *= m)
    const float w00 = wy0 * wx0 * vy0 * vx0 * mv;
    const float w01 = wy0 * wx1 * vy0 * vx1 * mv;
    const float w10 = wy1 * wx0 * vy1 * vx0 * mv;
    const float w11 = wy1 * wx1 * vy1 * vx1 * mv;

    const int x0c = min(max(x0, 0), Wn - 1);
    const int x1c = min(max(x1, 0), Wn - 1);
    const int y0c = min(max(y0, 0), Hn - 1);
    const int y1c = min(max(y1, 0), Hn - 1);

    const int o00 = y0c * Wn + x0c;
    const int o01 = y0c * Wn + x1c;
    const int o10 = y1c * Wn + x0c;
    const int o11 = y1c * Wn + x1c;

    const int base = (b * Cn + cg * CPT) * HWn;   // fits in int (max 33.5M)
    const float* __restrict__ xb = x_enc + base;
    float* __restrict__ ob = out + base;

#pragma unroll
    for (int c = 0; c < CPT; ++c) {
        const float* __restrict__ p = xb + c * HWn;
        const float v = w00 * p[o00] + w01 * p[o01]
                      + w10 * p[o10] + w11 * p[o11];
        ob[c * HWn + hw] = v;
    }
}

extern "C" void kernel_launch(void* const* d_in, const int* in_sizes, int n_in,
                              void* d_out, int out_size)
{
    const float* phi   = (const float*)d_in[0];
    const float* x_enc = (const float*)d_in[1];
    const float* m     = (const float*)d_in[2];
    float* out         = (float*)d_out;

    const int total_threads = NPIX * NCG;     // 4,194,304
    const int tpb = 256;
    const int blocks = total_threads / tpb;   // 16384
    warp_bilinear_kernel<<<blocks, tpb>>>(phi, x_enc, m, out);
}

// round 2
// speedup vs baseline: 1.9628x; 1.9628x over previous
#include <cuda_runtime.h>

// Problem constants (fixed by the reference): B=8, C=64, H=W=256.
#define Bn   8
#define Cn   64
#define Hn   256
#define Wn   256
#define HWn  (Hn * Wn)          // 65536
#define NPIX (Bn * HWn)         // 524288 = 2^19
#define CPT  8                  // channels per thread
#define NCG  (Cn / CPT)         // 8 channel groups

__global__ __launch_bounds__(256)
void warp_bilinear_kernel(const float* __restrict__ phi,
                          const float* __restrict__ x_enc,
                          const float* __restrict__ m,
                          float* __restrict__ out)
{
    // cg in LOW bits of blockIdx -> all 8 channel groups of a pixel tile run
    // concurrently, so phi/m reads hit L2 for 7 of 8 groups.
    const int cg       = blockIdx.x & (NCG - 1);
    const int pixBlock = blockIdx.x >> 3;
    const int pix      = pixBlock * blockDim.x + threadIdx.x;

    const int b   = pix >> 16;            // pix / HW
    const int hw  = pix & (HWn - 1);
    const int h   = hw >> 8;
    const int w   = hw & (Wn - 1);

    // Per-pixel (channel-invariant) sampling setup
    const float px = phi[(b * 2 + 0) * HWn + hw];
    const float py = phi[(b * 2 + 1) * HWn + hw];
    const float mv = m[b * HWn + hw];

    // vgrid = 2*(coord+phi)/(dim-1) - 1 + 2*phi ; unnormalize (align_corners=False)
    const float vx = 2.0f * ((float)w + px) / (float)(Wn - 1) - 1.0f + 2.0f * px;
    const float vy = 2.0f * ((float)h + py) / (float)(Hn - 1) - 1.0f + 2.0f * py;
    const float ix = (vx + 1.0f) * (0.5f * (float)Wn) - 0.5f;
    const float iy = (vy + 1.0f) * (0.5f * (float)Hn) - 0.5f;

    const float x0f = floorf(ix);
    const float y0f = floorf(iy);
    const int   x0  = (int)x0f;
    const int   y0  = (int)y0f;
    const int   x1  = x0 + 1;
    const int   y1  = y0 + 1;

    const float wx1 = ix - x0f;
    const float wx0 = 1.0f - wx1;
    const float wy1 = iy - y0f;
    const float wy0 = 1.0f - wy1;

    const float vx0 = (x0 >= 0 && x0 < Wn) ? 1.0f : 0.0f;
    const float vx1 = (x1 >= 0 && x1 < Wn) ? 1.0f : 0.0f;
    const float vy0 = (y0 >= 0 && y0 < Hn) ? 1.0f : 0.0f;
    const float vy1 = (y1 >= 0 && y1 < Hn) ? 1.0f : 0.0f;

    // Fold validity AND mask into the 4 corner weights (zeros padding, out *= m)
    const float w00 = wy0 * wx0 * vy0 * vx0 * mv;
    const float w01 = wy0 * wx1 * vy0 * vx1 * mv;
    const float w10 = wy1 * wx0 * vy1 * vx0 * mv;
    const float w11 = wy1 * wx1 * vy1 * vx1 * mv;

    const int base = (b * Cn + cg * CPT) * HWn;
    float* __restrict__ ob = out + base;

    // Fast path: every corner weight is zero (sample fully out of bounds,
    // degenerate weight, or m==0) -> output is exactly 0 for all channels.
    // This is the COMMON case here (phi*2 displacement pushes most samples
    // out of [-1,1]); it skips all 4*CPT gathers.
    const bool any = (w00 != 0.0f) | (w01 != 0.0f) | (w10 != 0.0f) | (w11 != 0.0f);

    if (!any) {
#pragma unroll
        for (int c = 0; c < CPT; ++c)
            ob[c * HWn + hw] = 0.0f;
        return;
    }

    const int x0c = min(max(x0, 0), Wn - 1);
    const int x1c = min(max(x1, 0), Wn - 1);
    const int y0c = min(max(y0, 0), Hn - 1);
    const int y1c = min(max(y1, 0), Hn - 1);

    const int o00 = y0c * Wn + x0c;
    const int o01 = y0c * Wn + x1c;
    const int o10 = y1c * Wn + x0c;
    const int o11 = y1c * Wn + x1c;

    const bool p00 = (w00 != 0.0f);
    const bool p01 = (w01 != 0.0f);
    const bool p10 = (w10 != 0.0f);
    const bool p11 = (w11 != 0.0f);

    const float* __restrict__ xb = x_enc + base;

#pragma unroll
    for (int c = 0; c < CPT; ++c) {
        const float* __restrict__ p = xb + c * HWn;
        float v = 0.0f;
        if (p00) v = fmaf(w00, __ldg(p + o00), v);   // predicated LDG: zero-weight
        if (p01) v = fmaf(w01, __ldg(p + o01), v);   // corners issue no memory op
        if (p10) v = fmaf(w10, __ldg(p + o10), v);
        if (p11) v = fmaf(w11, __ldg(p + o11), v);
        ob[c * HWn + hw] = v;
    }
}

extern "C" void kernel_launch(void* const* d_in, const int* in_sizes, int n_in,
                              void* d_out, int out_size)
{
    const float* phi   = (const float*)d_in[0];
    const float* x_enc = (const float*)d_in[1];
    const float* m     = (const float*)d_in[2];
    float* out         = (float*)d_out;

    const int total_threads = NPIX * NCG;     // 4,194,304
    const int tpb = 256;
    const int blocks = total_threads / tpb;   // 16384
    warp_bilinear_kernel<<<blocks, tpb>>>(phi, x_enc, m, out);
}